// round 11
// baseline (speedup 1.0000x reference)
#include <cuda_runtime.h>
#include <cuda_bf16.h>
#include <math.h>
#include <stdint.h>

#define N_TOK 4096
#define DIM   1024
#define NEXP  8
#define FDIM  2048
#define NPAIR (2*N_TOK)

// ---------------- device scratch (~80.2 MB, proven safe) ----------------
__device__ int   g_cnt[NEXP];
__device__ int   g_off[NEXP];
__device__ int   g_bucket[NEXP * N_TOK];
__device__ float g_pairw[NPAIR];
__device__ __nv_bfloat16 g_xh[(size_t)N_TOK * DIM];   // 8 MB
__device__ __nv_bfloat16 g_xl[(size_t)N_TOK * DIM];   // 8 MB
__device__ __nv_bfloat16 g_hh[(size_t)NPAIR * FDIM];  // 32 MB
__device__ __nv_bfloat16 g_hl[(size_t)NPAIR * FDIM];  // 32 MB

// ==================== helpers ====================
__device__ __forceinline__ uint32_t smem_u32(const void* p) {
    uint32_t a;
    asm("{ .reg .u64 t; cvta.to.shared.u64 t, %1; cvt.u32.u64 %0, t; }" : "=r"(a) : "l"(p));
    return a;
}
#define CP16(dst, src) \
    asm volatile("cp.async.ca.shared.global [%0], [%1], 16;" :: "r"(dst), "l"(src) : "memory")
#define CP_COMMIT() asm volatile("cp.async.commit_group;" ::: "memory")
#define CP_WAIT0()  asm volatile("cp.async.wait_group 0;" ::: "memory")
#define LDSM4(r0, r1, r2, r3, addr) \
    asm volatile("ldmatrix.sync.aligned.m8n8.x4.shared.b16 {%0,%1,%2,%3}, [%4];" \
                 : "=r"(r0), "=r"(r1), "=r"(r2), "=r"(r3) : "r"(addr) : "memory")

__device__ __forceinline__ void mma_bf16(float (&c)[4], const uint32_t* a, const uint32_t* b) {
    asm volatile(
        "mma.sync.aligned.m16n8k16.row.col.f32.bf16.bf16.f32 "
        "{%0,%1,%2,%3}, {%4,%5,%6,%7}, {%8,%9}, {%0,%1,%2,%3};"
        : "+f"(c[0]), "+f"(c[1]), "+f"(c[2]), "+f"(c[3])
        : "r"(a[0]), "r"(a[1]), "r"(a[2]), "r"(a[3]), "r"(b[0]), "r"(b[1]));
}

// error-free hi split (truncate) + RN lo residual, packed as two bf16x2 words
__device__ __forceinline__ void pack2(float v0, float v1, uint32_t& hp, uint32_t& lp) {
    uint32_t u0 = __float_as_uint(v0), u1 = __float_as_uint(v1);
    float l0 = v0 - __uint_as_float(u0 & 0xffff0000u);
    float l1 = v1 - __uint_as_float(u1 & 0xffff0000u);
    hp = (u0 >> 16) | (u1 & 0xffff0000u);
    lp = (uint32_t)__bfloat16_as_ushort(__float2bfloat16(l0)) |
         ((uint32_t)__bfloat16_as_ushort(__float2bfloat16(l1)) << 16);
}

// ==================== small kernels ====================
__global__ void zero_kernel() {
    if (threadIdx.x < NEXP) g_cnt[threadIdx.x] = 0;
}

__global__ void gate_kernel(const float* __restrict__ x,
                            const float* __restrict__ gw,
                            const float* __restrict__ gb) {
    int tok  = (blockIdx.x * blockDim.x + threadIdx.x) >> 5;
    int lane = threadIdx.x & 31;
    if (tok >= N_TOK) return;
    const float* xr = x + (size_t)tok * DIM;
    float acc[NEXP];
#pragma unroll
    for (int e = 0; e < NEXP; e++) acc[e] = 0.f;
    for (int d = lane; d < DIM; d += 32) {
        float xv = xr[d];
        const float4* g4 = reinterpret_cast<const float4*>(gw + (size_t)d * NEXP);
        float4 a = g4[0], b = g4[1];
        acc[0] += xv * a.x; acc[1] += xv * a.y; acc[2] += xv * a.z; acc[3] += xv * a.w;
        acc[4] += xv * b.x; acc[5] += xv * b.y; acc[6] += xv * b.z; acc[7] += xv * b.w;
    }
#pragma unroll
    for (int e = 0; e < NEXP; e++) {
#pragma unroll
        for (int s = 16; s > 0; s >>= 1)
            acc[e] += __shfl_xor_sync(0xffffffffu, acc[e], s);
    }
    if (lane == 0) {
        float lg[NEXP];
        float mx = -1e30f;
#pragma unroll
        for (int e = 0; e < NEXP; e++) { lg[e] = acc[e] + gb[e]; mx = fmaxf(mx, lg[e]); }
        float sum = 0.f;
#pragma unroll
        for (int e = 0; e < NEXP; e++) { lg[e] = expf(lg[e] - mx); sum += lg[e]; }
        float inv = 1.f / sum;
#pragma unroll
        for (int e = 0; e < NEXP; e++) lg[e] *= inv;
        int i0 = 0;
#pragma unroll
        for (int e = 1; e < NEXP; e++) if (lg[e] > lg[i0]) i0 = e;
        int i1 = -1;
#pragma unroll
        for (int e = 0; e < NEXP; e++)
            if (e != i0 && (i1 < 0 || lg[e] > lg[i1])) i1 = e;
        float e1 = expf(lg[i1] - lg[i0]);
        float is2 = 1.f / (1.f + e1);
        g_pairw[tok * 2 + 0] = is2;
        g_pairw[tok * 2 + 1] = e1 * is2;
        int p0 = atomicAdd(&g_cnt[i0], 1);
        g_bucket[i0 * N_TOK + p0] = tok * 2 + 0;
        int p1 = atomicAdd(&g_cnt[i1], 1);
        g_bucket[i1 * N_TOK + p1] = tok * 2 + 1;
    }
}

__global__ void prefix_kernel() {
    int s = 0;
#pragma unroll
    for (int e = 0; e < NEXP; e++) { g_off[e] = s; s += g_cnt[e]; }
}

// convx + zero-out fused (same index space)
__global__ void convx_kernel(const float* __restrict__ x, float* __restrict__ out) {
    size_t i = ((size_t)blockIdx.x * blockDim.x + threadIdx.x) * 4;
    float4 v = *(const float4*)(x + i);
    __nv_bfloat16 h0 = __float2bfloat16(v.x), h1 = __float2bfloat16(v.y);
    __nv_bfloat16 h2 = __float2bfloat16(v.z), h3 = __float2bfloat16(v.w);
    ushort4 hv = make_ushort4(__bfloat16_as_ushort(h0), __bfloat16_as_ushort(h1),
                              __bfloat16_as_ushort(h2), __bfloat16_as_ushort(h3));
    ushort4 lv = make_ushort4(
        __bfloat16_as_ushort(__float2bfloat16(v.x - __bfloat162float(h0))),
        __bfloat16_as_ushort(__float2bfloat16(v.y - __bfloat162float(h1))),
        __bfloat16_as_ushort(__float2bfloat16(v.z - __bfloat162float(h2))),
        __bfloat16_as_ushort(__float2bfloat16(v.w - __bfloat162float(h3))));
    *(ushort4*)(g_xh + i) = hv;
    *(ushort4*)(g_xl + i) = lv;
    *(float4*)(out + i) = make_float4(0.f, 0.f, 0.f, 0.f);
}

// ==================== GEMM config ====================
// BM=256 x BN=128 tile, BK=32, double-buffered, occ 1 (full 255-reg budget).
// 8 warps, each computes a 64x64 sub-tile (mt=4, nt=8).
// Buffer: Ah[256x80B] Al[256x80B] Bh[128x80B] Bl[128x80B]
#define ROWB   80
#define ATILE  (256 * ROWB)          // 20480
#define BTILE  (128 * ROWB)          // 10240
#define BHO    (2 * ATILE)           // 40960
#define BLO    (BHO + BTILE)         // 51200
#define BUFB   (BHO + 2 * BTILE)     // 61440
#define DSM    (2 * BUFB)            // 122880

// full-chunk compute: 2 k-halves; per half: 8 B-LDSM4 + 8 A-LDSM4 + 96 HMMA
#define GEMM_COMPUTE(bu)                                                           \
    _Pragma("unroll")                                                              \
    for (int ks = 0; ks < 2; ks++) {                                               \
        uint32_t bh[16], bl[16];                                                   \
        LDSM4(bh[0],  bh[1],  bh[2],  bh[3],  (bu) + BHO + boff + ks * 32);        \
        LDSM4(bh[4],  bh[5],  bh[6],  bh[7],  (bu) + BHO + boff + 1280 + ks * 32); \
        LDSM4(bh[8],  bh[9],  bh[10], bh[11], (bu) + BHO + boff + 2560 + ks * 32); \
        LDSM4(bh[12], bh[13], bh[14], bh[15], (bu) + BHO + boff + 3840 + ks * 32); \
        LDSM4(bl[0],  bl[1],  bl[2],  bl[3],  (bu) + BLO + boff + ks * 32);        \
        LDSM4(bl[4],  bl[5],  bl[6],  bl[7],  (bu) + BLO + boff + 1280 + ks * 32); \
        LDSM4(bl[8],  bl[9],  bl[10], bl[11], (bu) + BLO + boff + 2560 + ks * 32); \
        LDSM4(bl[12], bl[13], bl[14], bl[15], (bu) + BLO + boff + 3840 + ks * 32); \
        _Pragma("unroll")                                                          \
        for (int mt = 0; mt < 4; mt++) {                                           \
            uint32_t ah[4], al[4];                                                 \
            LDSM4(ah[0], ah[1], ah[2], ah[3], (bu) + aoff + mt * 1280 + ks * 32);  \
            LDSM4(al[0], al[1], al[2], al[3], (bu) + ATILE + aoff + mt * 1280 + ks * 32); \
            _Pragma("unroll")                                                      \
            for (int nt = 0; nt < 8; nt++) {                                       \
                mma_bf16(acc[mt][nt], ah, &bh[nt * 2]);                            \
                mma_bf16(acc[mt][nt], ah, &bl[nt * 2]);                            \
                mma_bf16(acc[mt][nt], al, &bh[nt * 2]);                            \
            }                                                                      \
        }                                                                          \
    }

// A fill: thread owns one full row (256 rows / 256 threads), 4 CP16 per plane
#define FILL_A_CP(bu, k0)                                                          \
    do {                                                                           \
        CP16((bu) + aDst,              (const char*)(pAh + (k0)));                 \
        CP16((bu) + aDst + 16,         (const char*)(pAh + (k0) + 8));             \
        CP16((bu) + aDst + 32,         (const char*)(pAh + (k0) + 16));            \
        CP16((bu) + aDst + 48,         (const char*)(pAh + (k0) + 24));            \
        CP16((bu) + ATILE + aDst,      (const char*)(pAl + (k0)));                 \
        CP16((bu) + ATILE + aDst + 16, (const char*)(pAl + (k0) + 8));             \
        CP16((bu) + ATILE + aDst + 32, (const char*)(pAl + (k0) + 16));            \
        CP16((bu) + ATILE + aDst + 48, (const char*)(pAl + (k0) + 24));            \
        CP_COMMIT();                                                               \
    } while (0)

// B staging: 16 k-values per thread (proven R7 pattern)
#define LDG_B(k0)                                                                  \
    _Pragma("unroll")                                                              \
    for (int j = 0; j < 16; j++) stg[j] = pW[(size_t)((k0) + kh * 16 + j) * ldw];

#define STS_B(bufc)                                                                \
    do {                                                                           \
        uint32_t* hp = (uint32_t*)(dsm + (bufc) + BHO + bDst);                     \
        uint32_t* lp = (uint32_t*)(dsm + (bufc) + BLO + bDst);                     \
        _Pragma("unroll")                                                          \
        for (int j = 0; j < 8; j++) {                                              \
            uint32_t h, l;                                                         \
            pack2(stg[2 * j], stg[2 * j + 1], h, l);                               \
            hp[j] = h; lp[j] = l;                                                  \
        }                                                                          \
    } while (0)

// ---------------- gemm1: H = relu(Xg @ w1 + b1) -> bf16 hi/lo planes ------
__global__ void __launch_bounds__(256)
gemm1_tc(const float* __restrict__ w1, const float* __restrict__ b1) {
    const int e   = blockIdx.z;
    const int cnt = g_cnt[e];
    const int m0  = blockIdx.y * 256;
    if (m0 >= cnt) return;
    const int n0   = blockIdx.x * 128;
    const int base = g_off[e];
    const int tid  = threadIdx.x;
    const int wid  = tid >> 5, lane = tid & 31;

    extern __shared__ __align__(128) char dsm[];
    const uint32_t s0 = smem_u32(dsm);

    // A fill: one row per thread
    const int ar = tid;
    const int* bkt = g_bucket + e * N_TOK;
    const int tok = __ldg(bkt + min(m0 + ar, cnt - 1)) >> 1;
    const __nv_bfloat16* pAh = g_xh + (size_t)tok * DIM;
    const __nv_bfloat16* pAl = g_xl + (size_t)tok * DIM;
    const uint32_t aDst = (uint32_t)(ar * ROWB);

    // B fill: bn = n column, kh = k half
    const int bn = tid & 127, kh = tid >> 7;
    const int ldw = FDIM;
    const float* pW = w1 + (size_t)e * DIM * FDIM + n0 + bn;
    const uint32_t bDst = (uint32_t)(bn * ROWB + kh * 32);

    // warp tiling: 4 warps in M x 2 in N; warp tile 64x64
    const int wm = (wid & 3) * 64, wn = (wid >> 2) * 64;
    const uint32_t aoff =
        (uint32_t)((wm + (lane & 7) + ((lane >> 3) & 1) * 8) * ROWB + (lane >> 4) * 16);
    const uint32_t boff =
        (uint32_t)((wn + (lane & 7) + ((lane >> 4) & 1) * 8) * ROWB + ((lane >> 3) & 1) * 16);

    float acc[4][8][4];
#pragma unroll
    for (int i = 0; i < 4; i++)
#pragma unroll
        for (int j = 0; j < 8; j++)
#pragma unroll
            for (int q = 0; q < 4; q++) acc[i][j][q] = 0.f;

    float stg[16];

    FILL_A_CP(s0, 0);
    LDG_B(0);
    STS_B(0);
    CP_WAIT0();
    __syncthreads();

    const int CH = DIM / 32;   // 32
    for (int c = 0; c < CH; c++) {
        const uint32_t bu   = s0 + (uint32_t)(c & 1) * BUFB;
        const uint32_t nxtO = (uint32_t)((c + 1) & 1) * BUFB;
        const bool more = (c + 1 < CH);
        if (more) {
            const int k0 = (c + 1) * 32;
            FILL_A_CP(s0 + nxtO, k0);
            LDG_B(k0);
        }
        GEMM_COMPUTE(bu);
        if (more) {
            STS_B(nxtO);
            CP_WAIT0();
            __syncthreads();
        }
    }

    // epilogue: +b1, relu, split to bf16 hi/lo planes
    const int gq = lane >> 2, tq = lane & 3;
#pragma unroll
    for (int nt = 0; nt < 8; nt++) {
        const int nc = n0 + wn + nt * 8 + tq * 2;
        const float bb0 = b1[e * FDIM + nc];
        const float bb1 = b1[e * FDIM + nc + 1];
#pragma unroll
        for (int mt = 0; mt < 4; mt++) {
            const int rl = wm + mt * 16 + gq;
#pragma unroll
            for (int hf = 0; hf < 2; hf++) {
                const int gr = m0 + rl + hf * 8;
                if (gr < cnt) {
                    float v0 = fmaxf(acc[mt][nt][hf * 2 + 0] + bb0, 0.f);
                    float v1 = fmaxf(acc[mt][nt][hf * 2 + 1] + bb1, 0.f);
                    size_t o = (size_t)(base + gr) * FDIM + nc;
                    __nv_bfloat16 h0 = __float2bfloat16(v0), h1 = __float2bfloat16(v1);
                    __nv_bfloat162 hv; hv.x = h0; hv.y = h1;
                    __nv_bfloat162 lv;
                    lv.x = __float2bfloat16(v0 - __bfloat162float(h0));
                    lv.y = __float2bfloat16(v1 - __bfloat162float(h1));
                    *(__nv_bfloat162*)&g_hh[o] = hv;
                    *(__nv_bfloat162*)&g_hl[o] = lv;
                }
            }
        }
    }
}

// ---------------- gemm2: out += (H @ w2 + b2) * pairw (atomic) ------------
__global__ void __launch_bounds__(256)
gemm2_tc(const float* __restrict__ w2, const float* __restrict__ b2,
         float* __restrict__ out) {
    const int e   = blockIdx.z;
    const int cnt = g_cnt[e];
    const int m0  = blockIdx.y * 256;
    if (m0 >= cnt) return;
    const int n0   = blockIdx.x * 128;
    const int base = g_off[e];
    const int tid  = threadIdx.x;
    const int wid  = tid >> 5, lane = tid & 31;

    extern __shared__ __align__(128) char dsm[];
    const uint32_t s0 = smem_u32(dsm);

    const int ar = tid;
    const int* bkt = g_bucket + e * N_TOK;
    const size_t arow = (size_t)(base + min(m0 + ar, cnt - 1)) * FDIM;
    const __nv_bfloat16* pAh = g_hh + arow;
    const __nv_bfloat16* pAl = g_hl + arow;
    const uint32_t aDst = (uint32_t)(ar * ROWB);

    const int bn = tid & 127, kh = tid >> 7;
    const int ldw = DIM;
    const float* pW = w2 + (size_t)e * FDIM * DIM + n0 + bn;
    const uint32_t bDst = (uint32_t)(bn * ROWB + kh * 32);

    const int wm = (wid & 3) * 64, wn = (wid >> 2) * 64;
    const uint32_t aoff =
        (uint32_t)((wm + (lane & 7) + ((lane >> 3) & 1) * 8) * ROWB + (lane >> 4) * 16);
    const uint32_t boff =
        (uint32_t)((wn + (lane & 7) + ((lane >> 4) & 1) * 8) * ROWB + ((lane >> 3) & 1) * 16);

    float acc[4][8][4];
#pragma unroll
    for (int i = 0; i < 4; i++)
#pragma unroll
        for (int j = 0; j < 8; j++)
#pragma unroll
            for (int q = 0; q < 4; q++) acc[i][j][q] = 0.f;

    float stg[16];

    FILL_A_CP(s0, 0);
    LDG_B(0);
    STS_B(0);
    CP_WAIT0();
    __syncthreads();

    const int CH = FDIM / 32;   // 64
    for (int c = 0; c < CH; c++) {
        const uint32_t bu   = s0 + (uint32_t)(c & 1) * BUFB;
        const uint32_t nxtO = (uint32_t)((c + 1) & 1) * BUFB;
        const bool more = (c + 1 < CH);
        if (more) {
            const int k0 = (c + 1) * 32;
            FILL_A_CP(s0 + nxtO, k0);
            LDG_B(k0);
        }
        GEMM_COMPUTE(bu);
        if (more) {
            STS_B(nxtO);
            CP_WAIT0();
            __syncthreads();
        }
    }

    // epilogue: (+b2) * combine weight, atomicAdd into out (2 adds/element,
    // commutative fp32 add -> bitwise deterministic)
    const int gq = lane >> 2, tq = lane & 3;
#pragma unroll
    for (int nt = 0; nt < 8; nt++) {
        const int nc = n0 + wn + nt * 8 + tq * 2;
        const float bb0 = b2[e * DIM + nc];
        const float bb1 = b2[e * DIM + nc + 1];
#pragma unroll
        for (int mt = 0; mt < 4; mt++) {
            const int rl = wm + mt * 16 + gq;
#pragma unroll
            for (int hf = 0; hf < 2; hf++) {
                const int gr = m0 + rl + hf * 8;
                if (gr < cnt) {
                    const int p = __ldg(bkt + gr);
                    const float w = g_pairw[p];
                    float* orow = out + (size_t)(p >> 1) * DIM + nc;
                    atomicAdd(orow,     (acc[mt][nt][hf * 2 + 0] + bb0) * w);
                    atomicAdd(orow + 1, (acc[mt][nt][hf * 2 + 1] + bb1) * w);
                }
            }
        }
    }
}

// ---------------- launch ----------------
extern "C" void kernel_launch(void* const* d_in, const int* in_sizes, int n_in,
                              void* d_out, int out_size) {
    const float* x  = (const float*)d_in[0];
    const float* gw = (const float*)d_in[1];
    const float* gb = (const float*)d_in[2];
    const float* w1 = (const float*)d_in[3];
    const float* b1 = (const float*)d_in[4];
    const float* w2 = (const float*)d_in[5];
    const float* b2 = (const float*)d_in[6];
    float* out = (float*)d_out;

    cudaFuncSetAttribute(gemm1_tc, cudaFuncAttributeMaxDynamicSharedMemorySize, DSM);
    cudaFuncSetAttribute(gemm2_tc, cudaFuncAttributeMaxDynamicSharedMemorySize, DSM);

    zero_kernel<<<1, 32>>>();
    gate_kernel<<<N_TOK / 8, 256>>>(x, gw, gb);
    prefix_kernel<<<1, 1>>>();
    convx_kernel<<<(N_TOK * DIM / 4) / 256, 256>>>(x, out);
    gemm1_tc<<<dim3(FDIM / 128, N_TOK / 256, NEXP), 256, DSM>>>(w1, b1);
    gemm2_tc<<<dim3(DIM / 128, N_TOK / 256, NEXP), 256, DSM>>>(w2, b2, out);
}

// round 12
// speedup vs baseline: 2.4760x; 2.4760x over previous
#include <cuda_runtime.h>
#include <cuda_fp16.h>
#include <math.h>
#include <stdint.h>

#define N_TOK 4096
#define DIM   1024
#define NEXP  8
#define FDIM  2048
#define NPAIR (2*N_TOK)

// ---------------- device scratch (~24.3 MB) ----------------
__device__ int    g_cnt[NEXP];
__device__ int    g_off[NEXP];
__device__ int    g_bucket[NEXP * N_TOK];
__device__ float  g_pairw[NPAIR];
__device__ __half g_xf[(size_t)N_TOK * DIM];    // 8 MB  (x as fp16)
__device__ __half g_hf[(size_t)NPAIR * FDIM];   // 16 MB (h as fp16)

// ==================== helpers ====================
__device__ __forceinline__ uint32_t smem_u32(const void* p) {
    uint32_t a;
    asm("{ .reg .u64 t; cvta.to.shared.u64 t, %1; cvt.u32.u64 %0, t; }" : "=r"(a) : "l"(p));
    return a;
}
#define CP16(dst, src) \
    asm volatile("cp.async.ca.shared.global [%0], [%1], 16;" :: "r"(dst), "l"(src) : "memory")
#define CP_COMMIT() asm volatile("cp.async.commit_group;" ::: "memory")
#define CP_WAIT0()  asm volatile("cp.async.wait_group 0;" ::: "memory")
#define LDSM4(r0, r1, r2, r3, addr) \
    asm volatile("ldmatrix.sync.aligned.m8n8.x4.shared.b16 {%0,%1,%2,%3}, [%4];" \
                 : "=r"(r0), "=r"(r1), "=r"(r2), "=r"(r3) : "r"(addr) : "memory")

__device__ __forceinline__ void mma_f16(float (&c)[4], const uint32_t* a, const uint32_t* b) {
    asm volatile(
        "mma.sync.aligned.m16n8k16.row.col.f32.f16.f16.f32 "
        "{%0,%1,%2,%3}, {%4,%5,%6,%7}, {%8,%9}, {%0,%1,%2,%3};"
        : "+f"(c[0]), "+f"(c[1]), "+f"(c[2]), "+f"(c[3])
        : "r"(a[0]), "r"(a[1]), "r"(a[2]), "r"(a[3]), "r"(b[0]), "r"(b[1]));
}

__device__ __forceinline__ uint32_t h2_bits(float v0, float v1) {
    __half2 h = __floats2half2_rn(v0, v1);
    return *(uint32_t*)&h;
}

// ==================== small kernels ====================
__global__ void zero_kernel() {
    if (threadIdx.x < NEXP) g_cnt[threadIdx.x] = 0;
}

__global__ void gate_kernel(const float* __restrict__ x,
                            const float* __restrict__ gw,
                            const float* __restrict__ gb) {
    int tok  = (blockIdx.x * blockDim.x + threadIdx.x) >> 5;
    int lane = threadIdx.x & 31;
    if (tok >= N_TOK) return;
    const float* xr = x + (size_t)tok * DIM;
    float acc[NEXP];
#pragma unroll
    for (int e = 0; e < NEXP; e++) acc[e] = 0.f;
    for (int d = lane; d < DIM; d += 32) {
        float xv = xr[d];
        const float4* g4 = reinterpret_cast<const float4*>(gw + (size_t)d * NEXP);
        float4 a = g4[0], b = g4[1];
        acc[0] += xv * a.x; acc[1] += xv * a.y; acc[2] += xv * a.z; acc[3] += xv * a.w;
        acc[4] += xv * b.x; acc[5] += xv * b.y; acc[6] += xv * b.z; acc[7] += xv * b.w;
    }
#pragma unroll
    for (int e = 0; e < NEXP; e++) {
#pragma unroll
        for (int s = 16; s > 0; s >>= 1)
            acc[e] += __shfl_xor_sync(0xffffffffu, acc[e], s);
    }
    if (lane == 0) {
        float lg[NEXP];
        float mx = -1e30f;
#pragma unroll
        for (int e = 0; e < NEXP; e++) { lg[e] = acc[e] + gb[e]; mx = fmaxf(mx, lg[e]); }
        float sum = 0.f;
#pragma unroll
        for (int e = 0; e < NEXP; e++) { lg[e] = expf(lg[e] - mx); sum += lg[e]; }
        float inv = 1.f / sum;
#pragma unroll
        for (int e = 0; e < NEXP; e++) lg[e] *= inv;
        int i0 = 0;
#pragma unroll
        for (int e = 1; e < NEXP; e++) if (lg[e] > lg[i0]) i0 = e;
        int i1 = -1;
#pragma unroll
        for (int e = 0; e < NEXP; e++)
            if (e != i0 && (i1 < 0 || lg[e] > lg[i1])) i1 = e;
        float e1 = expf(lg[i1] - lg[i0]);
        float is2 = 1.f / (1.f + e1);
        g_pairw[tok * 2 + 0] = is2;
        g_pairw[tok * 2 + 1] = e1 * is2;
        int p0 = atomicAdd(&g_cnt[i0], 1);
        g_bucket[i0 * N_TOK + p0] = tok * 2 + 0;
        int p1 = atomicAdd(&g_cnt[i1], 1);
        g_bucket[i1 * N_TOK + p1] = tok * 2 + 1;
    }
}

__global__ void prefix_kernel() {
    int s = 0;
#pragma unroll
    for (int e = 0; e < NEXP; e++) { g_off[e] = s; s += g_cnt[e]; }
}

// convx (fp32 -> fp16) + zero-out fused
__global__ void convx_kernel(const float* __restrict__ x, float* __restrict__ out) {
    size_t i = ((size_t)blockIdx.x * blockDim.x + threadIdx.x) * 4;
    float4 v = *(const float4*)(x + i);
    uint2 p;
    p.x = h2_bits(v.x, v.y);
    p.y = h2_bits(v.z, v.w);
    *(uint2*)(g_xf + i) = p;
    *(float4*)(out + i) = make_float4(0.f, 0.f, 0.f, 0.f);
}

// ==================== GEMM config ====================
// 128x128 tile, BK=32, double-buffered, fp16 single-term MMA, occ 2.
// Buffer: A[128 rows x 32 fp16 (64B) pad->80B] | B[128 x 32 fp16, 80B rows]
#define ROWB   80
#define TILEB  (128 * ROWB)      // 10240
#define BUFB   (2 * TILEB)       // 20480
#define DSM    (2 * BUFB)        // 40960

// full-chunk compute: 2 k-halves; per half: 2 B-LDSM4 + 4 A-LDSM4 + 16 HMMA
#define GEMM_COMPUTE(bu)                                                          \
    _Pragma("unroll")                                                             \
    for (int ks = 0; ks < 2; ks++) {                                              \
        uint32_t bh[8];                                                           \
        LDSM4(bh[0], bh[1], bh[2], bh[3], (bu) + TILEB + boff + ks * 32);         \
        LDSM4(bh[4], bh[5], bh[6], bh[7], (bu) + TILEB + boff + 1280 + ks * 32);  \
        _Pragma("unroll")                                                         \
        for (int mt = 0; mt < 4; mt++) {                                          \
            uint32_t ah[4];                                                       \
            LDSM4(ah[0], ah[1], ah[2], ah[3], (bu) + aoff + mt * 1280 + ks * 32); \
            _Pragma("unroll")                                                     \
            for (int nt = 0; nt < 4; nt++)                                        \
                mma_f16(acc[mt][nt], ah, &bh[nt * 2]);                            \
        }                                                                         \
    }

// A fill: thread -> (row ar=tid>>1, 16-elem half), 2 CP16 from fp16 plane
#define FILL_A_CP(bu, k0)                                                         \
    do {                                                                          \
        CP16((bu) + aDst,      (const char*)(pA + (k0) + half * 16));             \
        CP16((bu) + aDst + 16, (const char*)(pA + (k0) + half * 16 + 8));         \
        CP_COMMIT();                                                              \
    } while (0)

// B staging: 16 strided fp32 loads, convert to 8 half2 words
#define LDG_B(k0)                                                                 \
    _Pragma("unroll")                                                             \
    for (int j = 0; j < 16; j++) stg[j] = pW[(size_t)((k0) + kh * 16 + j) * ldw];

#define STS_B(bufc)                                                               \
    do {                                                                          \
        uint32_t* bp = (uint32_t*)(dsm + (bufc) + TILEB + bDst);                  \
        _Pragma("unroll")                                                         \
        for (int j = 0; j < 8; j++) bp[j] = h2_bits(stg[2 * j], stg[2 * j + 1]);  \
    } while (0)

// ---------------- gemm1: H = relu(Xg @ w1 + b1) -> fp16 plane -------------
__global__ void __launch_bounds__(256, 2)
gemm1_tc(const float* __restrict__ w1, const float* __restrict__ b1) {
    const int e   = blockIdx.z;
    const int cnt = g_cnt[e];
    const int m0  = blockIdx.y * 128;
    if (m0 >= cnt) return;
    const int n0   = blockIdx.x * 128;
    const int base = g_off[e];
    const int tid  = threadIdx.x;
    const int wid  = tid >> 5, lane = tid & 31;

    extern __shared__ __align__(128) char dsm[];
    const uint32_t s0 = smem_u32(dsm);

    const int ar = tid >> 1, half = tid & 1;
    const int tok = g_bucket[e * N_TOK + min(m0 + ar, cnt - 1)] >> 1;
    const __half* pA = g_xf + (size_t)tok * DIM;
    const uint32_t aDst = (uint32_t)(ar * ROWB + half * 32);

    const int bn = tid & 127, kh = tid >> 7;
    const int ldw = FDIM;
    const float* pW = w1 + (size_t)e * DIM * FDIM + n0 + bn;
    const uint32_t bDst = (uint32_t)(bn * ROWB + kh * 32);

    const int wm = (wid & 1) * 64, wn = (wid >> 1) * 32;
    const uint32_t aoff =
        (uint32_t)((wm + (lane & 7) + ((lane >> 3) & 1) * 8) * ROWB + (lane >> 4) * 16);
    const uint32_t boff =
        (uint32_t)((wn + (lane & 7) + ((lane >> 4) & 1) * 8) * ROWB + ((lane >> 3) & 1) * 16);

    float acc[4][4][4];
#pragma unroll
    for (int i = 0; i < 4; i++)
#pragma unroll
        for (int j = 0; j < 4; j++)
#pragma unroll
            for (int q = 0; q < 4; q++) acc[i][j][q] = 0.f;

    float stg[16];

    FILL_A_CP(s0, 0);
    LDG_B(0);
    STS_B(0);
    CP_WAIT0();
    __syncthreads();

    const int CH = DIM / 32;   // 32
    for (int c = 0; c < CH; c++) {
        const uint32_t bu   = s0 + (uint32_t)(c & 1) * BUFB;
        const uint32_t nxtO = (uint32_t)((c + 1) & 1) * BUFB;
        const bool more = (c + 1 < CH);
        if (more) {
            const int k0 = (c + 1) * 32;
            FILL_A_CP(s0 + nxtO, k0);
            LDG_B(k0);
        }
        GEMM_COMPUTE(bu);
        if (more) {
            STS_B(nxtO);
            CP_WAIT0();
            __syncthreads();
        }
    }

    // epilogue: +b1, relu, store h as fp16
    const int gq = lane >> 2, tq = lane & 3;
#pragma unroll
    for (int nt = 0; nt < 4; nt++) {
        const int nc = n0 + wn + nt * 8 + tq * 2;
        const float bb0 = b1[e * FDIM + nc];
        const float bb1 = b1[e * FDIM + nc + 1];
#pragma unroll
        for (int mt = 0; mt < 4; mt++) {
            const int rl = wm + mt * 16 + gq;
#pragma unroll
            for (int hf = 0; hf < 2; hf++) {
                const int gr = m0 + rl + hf * 8;
                if (gr < cnt) {
                    float v0 = fmaxf(acc[mt][nt][hf * 2 + 0] + bb0, 0.f);
                    float v1 = fmaxf(acc[mt][nt][hf * 2 + 1] + bb1, 0.f);
                    size_t o = (size_t)(base + gr) * FDIM + nc;
                    *(uint32_t*)&g_hf[o] = h2_bits(v0, v1);
                }
            }
        }
    }
}

// ---------------- gemm2: out += (H @ w2 + b2) * pairw (atomic) ------------
__global__ void __launch_bounds__(256, 2)
gemm2_tc(const float* __restrict__ w2, const float* __restrict__ b2,
         float* __restrict__ out) {
    const int e   = blockIdx.z;
    const int cnt = g_cnt[e];
    const int m0  = blockIdx.y * 128;
    if (m0 >= cnt) return;
    const int n0   = blockIdx.x * 128;
    const int base = g_off[e];
    const int tid  = threadIdx.x;
    const int wid  = tid >> 5, lane = tid & 31;

    extern __shared__ __align__(128) char dsm[];
    const uint32_t s0 = smem_u32(dsm);

    const int ar = tid >> 1, half = tid & 1;
    const __half* pA = g_hf + (size_t)(base + min(m0 + ar, cnt - 1)) * FDIM;
    const uint32_t aDst = (uint32_t)(ar * ROWB + half * 32);

    const int bn = tid & 127, kh = tid >> 7;
    const int ldw = DIM;
    const float* pW = w2 + (size_t)e * FDIM * DIM + n0 + bn;
    const uint32_t bDst = (uint32_t)(bn * ROWB + kh * 32);

    const int wm = (wid & 1) * 64, wn = (wid >> 1) * 32;
    const uint32_t aoff =
        (uint32_t)((wm + (lane & 7) + ((lane >> 3) & 1) * 8) * ROWB + (lane >> 4) * 16);
    const uint32_t boff =
        (uint32_t)((wn + (lane & 7) + ((lane >> 4) & 1) * 8) * ROWB + ((lane >> 3) & 1) * 16);

    float acc[4][4][4];
#pragma unroll
    for (int i = 0; i < 4; i++)
#pragma unroll
        for (int j = 0; j < 4; j++)
#pragma unroll
            for (int q = 0; q < 4; q++) acc[i][j][q] = 0.f;

    float stg[16];

    FILL_A_CP(s0, 0);
    LDG_B(0);
    STS_B(0);
    CP_WAIT0();
    __syncthreads();

    const int CH = FDIM / 32;   // 64
    for (int c = 0; c < CH; c++) {
        const uint32_t bu   = s0 + (uint32_t)(c & 1) * BUFB;
        const uint32_t nxtO = (uint32_t)((c + 1) & 1) * BUFB;
        const bool more = (c + 1 < CH);
        if (more) {
            const int k0 = (c + 1) * 32;
            FILL_A_CP(s0 + nxtO, k0);
            LDG_B(k0);
        }
        GEMM_COMPUTE(bu);
        if (more) {
            STS_B(nxtO);
            CP_WAIT0();
            __syncthreads();
        }
    }

    // epilogue: (+b2) * combine weight, atomicAdd into out (2 adds/element,
    // commutative fp32 add -> bitwise deterministic)
    const int gq = lane >> 2, tq = lane & 3;
#pragma unroll
    for (int nt = 0; nt < 4; nt++) {
        const int nc = n0 + wn + nt * 8 + tq * 2;
        const float bb0 = b2[e * DIM + nc];
        const float bb1 = b2[e * DIM + nc + 1];
#pragma unroll
        for (int mt = 0; mt < 4; mt++) {
            const int rl = wm + mt * 16 + gq;
#pragma unroll
            for (int hf = 0; hf < 2; hf++) {
                const int gr = m0 + rl + hf * 8;
                if (gr < cnt) {
                    const int p = g_bucket[e * N_TOK + gr];
                    const float w = g_pairw[p];
                    float* orow = out + (size_t)(p >> 1) * DIM + nc;
                    atomicAdd(orow,     (acc[mt][nt][hf * 2 + 0] + bb0) * w);
                    atomicAdd(orow + 1, (acc[mt][nt][hf * 2 + 1] + bb1) * w);
                }
            }
        }
    }
}

// ---------------- launch ----------------
extern "C" void kernel_launch(void* const* d_in, const int* in_sizes, int n_in,
                              void* d_out, int out_size) {
    const float* x  = (const float*)d_in[0];
    const float* gw = (const float*)d_in[1];
    const float* gb = (const float*)d_in[2];
    const float* w1 = (const float*)d_in[3];
    const float* b1 = (const float*)d_in[4];
    const float* w2 = (const float*)d_in[5];
    const float* b2 = (const float*)d_in[6];
    float* out = (float*)d_out;

    cudaFuncSetAttribute(gemm1_tc, cudaFuncAttributeMaxDynamicSharedMemorySize, DSM);
    cudaFuncSetAttribute(gemm2_tc, cudaFuncAttributeMaxDynamicSharedMemorySize, DSM);

    zero_kernel<<<1, 32>>>();
    gate_kernel<<<N_TOK / 8, 256>>>(x, gw, gb);
    prefix_kernel<<<1, 1>>>();
    convx_kernel<<<(N_TOK * DIM / 4) / 256, 256>>>(x, out);
    gemm1_tc<<<dim3(FDIM / 128, N_TOK / 128, NEXP), 256, DSM>>>(w1, b1);
    gemm2_tc<<<dim3(DIM / 128, N_TOK / 128, NEXP), 256, DSM>>>(w2, b2, out);
}